// round 17
// baseline (speedup 1.0000x reference)
#include <cuda_runtime.h>
#include <cuda_bf16.h>
#include <cuda_fp16.h>
#include <math.h>
#include <stdint.h>

// Problem constants
#define B_   16
#define L_   128
#define KW   8
#define NPAIR 2104
#define GCN  512
#define PE   64
#define PF   1088
#define PFP  1152
#define M_   2048
#define NREL 17

// ---------------- scratch ----------------------------------------------------
__device__ __half g_AemoH[M_ * PF];        // GEMM output fp16
__device__ __half g_AcauH[M_ * PF];
__device__ __half g_AposH[NREL * PF];      // positional+bias table fp16
__device__ int    g_poff[L_];
__device__ __half g_Ah[2][M_ * GCN];       // A fp16
__device__ __half g_Bh[2][PFP * GCN];      // B fp16

// ---------------- init: pair offsets + emo_cau_pos tail ----------------------
__global__ void init_pairs_kernel(float* __restrict__ out, int out_size) {
    int i = threadIdx.x;
    if (i >= L_) return;
    int off = 0;
    for (int t = 0; t < i; t++) {
        int lo = t - KW; if (lo < 0) lo = 0;
        int hi = t + KW; if (hi > L_ - 1) hi = L_ - 1;
        off += hi - lo + 1;
    }
    g_poff[i] = off;
    int lo = i - KW; if (lo < 0) lo = 0;
    int hi = i + KW; if (hi > L_ - 1) hi = L_ - 1;
    if (out_size == B_ * NPAIR + 2 * NPAIR) {
        for (int j = lo; j <= hi; j++) {
            int p = off + (j - lo);
            out[B_ * NPAIR + 2 * p + 0] = (float)(i + 1);
            out[B_ * NPAIR + 2 * p + 1] = (float)(j + 1);
        }
    }
}

// ------- init: Apos table (f computed in smem, one block per r) --------------
__global__ void init_tables_kernel(const float* __restrict__ pos_emb,
                                   const float* __restrict__ W1,
                                   const float* __restrict__ b1) {
    __shared__ float sf[PE];
    const int r = blockIdx.x;          // 0..16
    const int tid = threadIdx.x;       // 256

    if (tid < PE) {
        float s = 0.f;
        #pragma unroll
        for (int d = 0; d < NREL; d++) {
            int ad = d - KW; if (ad < 0) ad = -ad;
            float cnt = (float)(L_ - ad);
            int dd = r - d;
            s += cnt * expf(-(float)(dd * dd)) * pos_emb[d * PE + tid];
        }
        sf[tid] = s;
    }
    __syncthreads();

    for (int g = tid; g < PF; g += 256) {
        float s = b1[g];
        const float* w = W1 + (size_t)g * PF + 2 * GCN;
        #pragma unroll 8
        for (int e = 0; e < PE; e++) s += sf[e] * w[e];
        g_AposH[r * PF + g] = __float2half_rn(s);
    }
}

// ---------------- merged convert: X and W1 -> fp16 ---------------------------
#define XBLK (M_ * GCN / 4 / 256)        // 1024 blocks for X portion
#define WBLK (PF * GCN / 4 / 256)        // 1088 blocks for W portion

__global__ void conv_all_kernel(const float* __restrict__ Xe,
                                const float* __restrict__ Xc,
                                const float* __restrict__ W1) {
    int blk = blockIdx.x;
    if (blk < XBLK) {
        int idx = blk * 256 + threadIdx.x;
        #pragma unroll
        for (int z = 0; z < 2; z++) {
            const float* X = z ? Xc : Xe;
            float4 v = *(const float4*)(X + (size_t)idx * 4);
            __half2* hp = (__half2*)(&g_Ah[z][(size_t)idx * 4]);
            hp[0] = __floats2half2_rn(v.x, v.y);
            hp[1] = __floats2half2_rn(v.z, v.w);
        }
    } else {
        int idx = (blk - XBLK) * 256 + threadIdx.x;
        int g = idx / (GCN / 4), kq = idx % (GCN / 4);
        #pragma unroll
        for (int z = 0; z < 2; z++) {
            float4 v = *(const float4*)(W1 + (size_t)g * PF + z * GCN + kq * 4);
            __half2* hp = (__half2*)(&g_Bh[z][(size_t)g * GCN + kq * 4]);
            hp[0] = __floats2half2_rn(v.x, v.y);
            hp[1] = __floats2half2_rn(v.z, v.w);
        }
    }
}

// ------ fp16 tensor-core GEMM: 128x128x32, single pass, 3-stage --------------
#define BM 128
#define BN 128
#define BK 32
#define SSTR 40
#define NBASE 16
#define NSTAGE 3
#define TILE_E (BM * SSTR)
#define STAGE_ELEMS (2 * TILE_E)        // A, B

__device__ __forceinline__ void cp16(void* smem, const void* g) {
    unsigned s = (unsigned)__cvta_generic_to_shared(smem);
    asm volatile("cp.async.cg.shared.global [%0], [%1], 16;\n" :: "r"(s), "l"(g));
}
#define CP_COMMIT() asm volatile("cp.async.commit_group;\n" ::: "memory")
#define CP_WAIT1()  asm volatile("cp.async.wait_group 1;\n" ::: "memory")

__device__ __forceinline__ void ldsm4(unsigned& r0, unsigned& r1,
                                      unsigned& r2, unsigned& r3,
                                      const __half* p) {
    unsigned a = (unsigned)__cvta_generic_to_shared(p);
    asm volatile("ldmatrix.sync.aligned.m8n8.x4.shared.b16 {%0,%1,%2,%3}, [%4];\n"
                 : "=r"(r0), "=r"(r1), "=r"(r2), "=r"(r3) : "r"(a));
}

extern __shared__ __align__(16) unsigned char dynraw[];

__global__ void __launch_bounds__(256, 2)
mma_gemm_kernel() {
    __half* dynsmem = (__half*)dynraw;
    const int z = blockIdx.z;
    const __half* __restrict__ Ah = g_Ah[z];
    const __half* __restrict__ Bh = g_Bh[z];
    __half* __restrict__ C = z ? g_AcauH : g_AemoH;

    const int tid  = threadIdx.x;
    const int lane = tid & 31;
    const int wid  = tid >> 5;
    const int wmBase = (wid & 1) * 64;
    const int wnBase = (wid >> 1) * 32;
    const int m0 = blockIdx.y * BM;
    const int n0 = blockIdx.x * BN;

    const int aRow = (lane & 7) + ((lane >> 3) & 1) * 8;
    const int aK   = (lane >> 4) * 8;
    const int bRow = (lane & 7) + (lane >> 4) * 8;
    const int bK   = ((lane >> 3) & 1) * 8;

    float acc[4][4][4];
    #pragma unroll
    for (int mt = 0; mt < 4; mt++)
        #pragma unroll
        for (int nt = 0; nt < 4; nt++)
            #pragma unroll
            for (int e = 0; e < 4; e++) acc[mt][nt][e] = 0.f;

    auto load_stage = [&](int kt, int s) {
        const int kc = kt * BK;
        __half* sA = dynsmem + s * STAGE_ELEMS;
        __half* sB = sA + TILE_E;
        #pragma unroll
        for (int l = 0; l < 2; l++) {
            int q = tid + l * 256;
            int row = q >> 2, c8 = (q & 3) * 8;
            cp16(&sA[row * SSTR + c8], Ah + (size_t)(m0 + row) * GCN + kc + c8);
            cp16(&sB[row * SSTR + c8], Bh + (size_t)(n0 + row) * GCN + kc + c8);
        }
    };

    load_stage(0, 0); CP_COMMIT();
    load_stage(1, 1); CP_COMMIT();

    for (int kt = 0; kt < NBASE; kt++) {
        CP_WAIT1();
        __syncthreads();
        if (kt + 2 < NBASE) load_stage(kt + 2, (kt + 2) % NSTAGE);
        CP_COMMIT();

        const int s = kt % NSTAGE;
        const __half* sA = dynsmem + s * STAGE_ELEMS;
        const __half* sB = sA + TILE_E;

        #pragma unroll
        for (int kk = 0; kk < BK; kk += 16) {
            unsigned a[4][4], b[2][4];
            #pragma unroll
            for (int mt = 0; mt < 4; mt++)
                ldsm4(a[mt][0], a[mt][1], a[mt][2], a[mt][3],
                      &sA[(wmBase + mt * 16 + aRow) * SSTR + kk + aK]);
            #pragma unroll
            for (int ntp = 0; ntp < 2; ntp++)
                ldsm4(b[ntp][0], b[ntp][1], b[ntp][2], b[ntp][3],
                      &sB[(wnBase + ntp * 16 + bRow) * SSTR + kk + bK]);
            #pragma unroll
            for (int mt = 0; mt < 4; mt++)
                #pragma unroll
                for (int nt = 0; nt < 4; nt++) {
                    unsigned b0 = b[nt >> 1][(nt & 1) * 2];
                    unsigned b1 = b[nt >> 1][(nt & 1) * 2 + 1];
                    asm volatile(
                        "mma.sync.aligned.m16n8k16.row.col.f32.f16.f16.f32 "
                        "{%0,%1,%2,%3}, {%4,%5,%6,%7}, {%8,%9}, {%0,%1,%2,%3};\n"
                        : "+f"(acc[mt][nt][0]), "+f"(acc[mt][nt][1]),
                          "+f"(acc[mt][nt][2]), "+f"(acc[mt][nt][3])
                        : "r"(a[mt][0]), "r"(a[mt][1]), "r"(a[mt][2]), "r"(a[mt][3]),
                          "r"(b0), "r"(b1));
                }
        }
    }

    #pragma unroll
    for (int mt = 0; mt < 4; mt++) {
        int row = m0 + wmBase + mt * 16 + (lane >> 2);
        #pragma unroll
        for (int nt = 0; nt < 4; nt++) {
            int col = n0 + wnBase + nt * 8 + (lane & 3) * 2;
            if (col < PF) {
                *(__half2*)&C[(size_t)row * PF + col] =
                    __floats2half2_rn(acc[mt][nt][0], acc[mt][nt][1]);
                *(__half2*)&C[(size_t)(row + 8) * PF + col] =
                    __floats2half2_rn(acc[mt][nt][2], acc[mt][nt][3]);
            }
        }
    }
}

// ---------------- epilogue: warp/(b,i,4j), fp16 h-math, W2 f32 in smem -------
#define WPI 5
#define TOTW (B_ * L_ * WPI)

__global__ void __launch_bounds__(256)
epilogue_kernel(const float* __restrict__ W2, const float* __restrict__ b2,
                float* __restrict__ out) {
    __shared__ __align__(16) float sW[PF];

    const int tid  = threadIdx.x;
    const int lane = tid & 31;
    const int wid  = tid >> 5;

    {
        const float4* src = (const float4*)W2;
        float4* dst = (float4*)sW;
        for (int q = tid; q < PF / 4; q += 256) dst[q] = src[q];
    }
    __syncthreads();

    int gw = blockIdx.x * 8 + wid;
    if (gw >= TOTW) return;
    int b   = gw / (L_ * WPI);
    int rem = gw - b * (L_ * WPI);
    int i   = rem / WPI;
    int k   = rem - i * WPI;

    int lo = i - KW; if (lo < 0) lo = 0;
    int hi = i + KW; if (hi > L_ - 1) hi = L_ - 1;
    int jstart = lo + 4 * k;
    if (jstart > hi) return;
    int cnt = hi - jstart + 1; if (cnt > 4) cnt = 4;

    int js0 = jstart;
    int js1 = jstart + 1 > hi ? hi : jstart + 1;
    int js2 = jstart + 2 > hi ? hi : jstart + 2;
    int js3 = jstart + 3 > hi ? hi : jstart + 3;

    const uint2* __restrict__ ac0 = (const uint2*)(g_AcauH + (size_t)(b * L_ + js0) * PF);
    const uint2* __restrict__ ac1 = (const uint2*)(g_AcauH + (size_t)(b * L_ + js1) * PF);
    const uint2* __restrict__ ac2 = (const uint2*)(g_AcauH + (size_t)(b * L_ + js2) * PF);
    const uint2* __restrict__ ac3 = (const uint2*)(g_AcauH + (size_t)(b * L_ + js3) * PF);
    const uint2* __restrict__ ap0 = (const uint2*)(g_AposH + (size_t)(js0 - i + KW) * PF);
    const uint2* __restrict__ ap1 = (const uint2*)(g_AposH + (size_t)(js1 - i + KW) * PF);
    const uint2* __restrict__ ap2 = (const uint2*)(g_AposH + (size_t)(js2 - i + KW) * PF);
    const uint2* __restrict__ ap3 = (const uint2*)(g_AposH + (size_t)(js3 - i + KW) * PF);
    const float4* __restrict__ sw4 = (const float4*)sW;

    // emo row into registers (fp16 packed: 4 feats per uint2)
    uint2 er[9];
    {
        const uint2* ae = (const uint2*)(g_AemoH + (size_t)(b * L_ + i) * PF);
        #pragma unroll
        for (int t = 0; t < 9; t++) {
            int c4 = t * 32 + lane;
            if (c4 < PF / 4) er[t] = ae[c4];
            else { er[t].x = 0u; er[t].y = 0u; }
        }
    }
    const float bias = __ldg(b2);
    const __half2 z2 = __half2half2(__ushort_as_half(0));

    float s0 = 0.f, s1 = 0.f, s2 = 0.f, s3 = 0.f;

    #pragma unroll
    for (int t = 0; t < 9; t++) {
        int c4 = t * 32 + lane;
        if (c4 < PF / 4) {
            uint2 e = er[t];
            float4 w = sw4[c4];
            __half2 ea = *(__half2*)&e.x;
            __half2 eb = *(__half2*)&e.y;

            #define DO_STREAM(acp, app, acc)                                   \
            {                                                                  \
                uint2 c = acp[c4]; uint2 q = app[c4];                          \
                __half2 ha = __hmax2(__hadd2(__hadd2(ea, *(__half2*)&c.x),     \
                                             *(__half2*)&q.x), z2);            \
                __half2 hb = __hmax2(__hadd2(__hadd2(eb, *(__half2*)&c.y),     \
                                             *(__half2*)&q.y), z2);            \
                float2 fa = __half22float2(ha);                                \
                float2 fb = __half22float2(hb);                                \
                acc = fmaf(fa.x, w.x, acc);                                    \
                acc = fmaf(fa.y, w.y, acc);                                    \
                acc = fmaf(fb.x, w.z, acc);                                    \
                acc = fmaf(fb.y, w.w, acc);                                    \
            }
            DO_STREAM(ac0, ap0, s0)
            DO_STREAM(ac1, ap1, s1)
            DO_STREAM(ac2, ap2, s2)
            DO_STREAM(ac3, ap3, s3)
            #undef DO_STREAM
        }
    }

    #pragma unroll
    for (int o = 16; o > 0; o >>= 1) {
        s0 += __shfl_xor_sync(0xFFFFFFFF, s0, o);
        s1 += __shfl_xor_sync(0xFFFFFFFF, s1, o);
        s2 += __shfl_xor_sync(0xFFFFFFFF, s2, o);
        s3 += __shfl_xor_sync(0xFFFFFFFF, s3, o);
    }
    if (lane == 0) {
        int pb = b * NPAIR + g_poff[i] + (jstart - lo);
        out[pb] = s0 + bias;
        if (cnt > 1) out[pb + 1] = s1 + bias;
        if (cnt > 2) out[pb + 2] = s2 + bias;
        if (cnt > 3) out[pb + 3] = s3 + bias;
    }
}

// ---------------- launch ------------------------------------------------------
extern "C" void kernel_launch(void* const* d_in, const int* in_sizes, int n_in,
                              void* d_out, int out_size) {
    const float* h_emo  = (const float*)d_in[0];
    const float* h_cau  = (const float*)d_in[1];
    const float* pos    = (const float*)d_in[2];
    const float* W1     = (const float*)d_in[3];
    const float* b1     = (const float*)d_in[4];
    const float* W2     = (const float*)d_in[5];
    const float* b2     = (const float*)d_in[6];
    float* out = (float*)d_out;

    const int gemm_smem = NSTAGE * STAGE_ELEMS * (int)sizeof(__half);
    static bool configured = false;
    if (!configured) {
        cudaFuncSetAttribute(mma_gemm_kernel,
                             cudaFuncAttributeMaxDynamicSharedMemorySize, gemm_smem);
        configured = true;
    }

    init_pairs_kernel<<<1, 128>>>(out, out_size);
    init_tables_kernel<<<NREL, 256>>>(pos, W1, b1);
    conv_all_kernel<<<XBLK + WBLK, 256>>>(h_emo, h_cau, W1);

    dim3 ggrid(PFP / BN, M_ / BM, 2);   // (9, 16, 2)
    mma_gemm_kernel<<<ggrid, 256, gemm_smem>>>();

    int blocks = (TOTW * 32 + 255) / 256;   // 1280 blocks
    epilogue_kernel<<<blocks, 256>>>(W2, b2, out);
}